// round 11
// baseline (speedup 1.0000x reference)
#include <cuda_runtime.h>
#include <cuda_bf16.h>
#include <cstdint>
#include <cstddef>

// Problem constants
#define BB   16
#define WW   64
#define VV   64
#define DD   256
#define RR   64
#define NN   (WW*VV)          // 4096
#define PAD  68               // padded stride for d-major GEMM1 tiles

typedef unsigned long long ull;

// ---------------------------------------------------------------------------
// Scratch (static device globals)
// ---------------------------------------------------------------------------
__device__ float g_A   [BB*WW*DD];
__device__ float g_BtT [BB*DD*VV];
__device__ float g_relaT[DD*RR];
__device__ float g_AW  [BB*WW*DD];
__device__ float g_BW  [BB*VV*DD];
__device__ float g_RW  [RR*DD];
__device__ uint32_t g_w1bT [DD*DD/2];            // w1^T bf16 pairs [n][kpair 128]
__device__ uint32_t g_rwbHi[DD*RR/2];            // RW^T bf16-hi pairs [n][kpair 32]
__device__ uint32_t g_rwbLo[DD*RR/2];            // RW^T bf16-lo pairs
__device__ __nv_bfloat16 g_tvh[(size_t)BB*NN*DD]; // tuple_vec bf16 (32 MB)
__device__ float g_att [BB*NN];
__device__ float g_fuse[BB*DD];

// ---------------------------------------------------------------------------
// helpers
// ---------------------------------------------------------------------------
__device__ __forceinline__ float tanh_fast(float x) {
    float y; asm("tanh.approx.f32 %0, %1;" : "=f"(y) : "f"(x)); return y;
}
__device__ __forceinline__ ull fma2(ull a, ull b, ull c) {
    ull d; asm("fma.rn.f32x2 %0, %1, %2, %3;" : "=l"(d) : "l"(a), "l"(b), "l"(c)); return d;
}
__device__ __forceinline__ ull pack2(float x) {
    ull r; asm("mov.b64 %0, {%1, %1};" : "=l"(r) : "f"(x)); return r;
}
__device__ __forceinline__ float2 unpack2(ull v) {
    float2 f; asm("mov.b64 {%0, %1}, %2;" : "=f"(f.x), "=f"(f.y) : "l"(v)); return f;
}
__device__ __forceinline__ uint32_t smem_u32(const void* p) {
    uint32_t a;
    asm("{ .reg .u64 tmp; cvta.to.shared.u64 tmp, %1; cvt.u32.u64 %0, tmp; }"
        : "=r"(a) : "l"(p));
    return a;
}
__device__ __forceinline__ void cp_async16(uint32_t daddr, const void* src) {
    asm volatile("cp.async.cg.shared.global [%0], [%1], 16;"
                 :: "r"(daddr), "l"(src) : "memory");
}
#define CP_COMMIT() asm volatile("cp.async.commit_group;" ::: "memory")
#define CP_WAIT0()  asm volatile("cp.async.wait_group 0;" ::: "memory")
#define CP_WAIT1()  asm volatile("cp.async.wait_group 1;" ::: "memory")

// m16n8k16 bf16 MMA (HMMA path; sm_80+, not an 'a' feature)
__device__ __forceinline__ void mma_bf16(float c[4],
    uint32_t a0, uint32_t a1, uint32_t a2, uint32_t a3,
    uint32_t b0, uint32_t b1)
{
    asm volatile(
        "mma.sync.aligned.m16n8k16.row.col.f32.bf16.bf16.f32 "
        "{%0,%1,%2,%3}, {%4,%5,%6,%7}, {%8,%9}, {%0,%1,%2,%3};"
        : "+f"(c[0]), "+f"(c[1]), "+f"(c[2]), "+f"(c[3])
        : "r"(a0), "r"(a1), "r"(a2), "r"(a3), "r"(b0), "r"(b1));
}

// pack two floats into bf16x2 u32 (low = first elem)
__device__ __forceinline__ uint32_t pkbf2(float a, float b) {
    return (uint32_t)__bfloat16_as_ushort(__float2bfloat16_rn(a))
         | ((uint32_t)__bfloat16_as_ushort(__float2bfloat16_rn(b)) << 16);
}
__device__ __forceinline__ float bf16hi_f(float x) {
    return __bfloat162float(__float2bfloat16_rn(x));
}

// ---------------------------------------------------------------------------
// Kernel W: g_w1bT[n][p] = bf16 pair (w1[2p][n], w1[2p+1][n]). 128 x 256.
// ---------------------------------------------------------------------------
__global__ __launch_bounds__(256) void kW1T(const float* __restrict__ aw1)
{
    const int p = blockIdx.x;
    const int n = threadIdx.x;
    const float a = aw1[(2 * p) * DD + n];
    const float b = aw1[(2 * p + 1) * DD + n];
    g_w1bT[n * 128 + p] = pkbf2(a, b);
}

// ---------------------------------------------------------------------------
// Kernel RT: RW^T hi/lo bf16 pair images. Runs AFTER kPre. 32 x 256.
// ---------------------------------------------------------------------------
__global__ __launch_bounds__(256) void kRWT()
{
    const int p = blockIdx.x;     // 0..31 (k pairs over R=64)
    const int n = threadIdx.x;    // 0..255 (output col)
    const float a = g_RW[(2 * p) * DD + n];
    const float b = g_RW[(2 * p + 1) * DD + n];
    g_rwbHi[n * 32 + p] = pkbf2(a, b);
    g_rwbLo[n * 32 + p] = pkbf2(a - bf16hi_f(a), b - bf16hi_f(b));
}

// ---------------------------------------------------------------------------
// Kernel P: gather + AW/BW/RW precompute + transposed copies (132 blocks)
// ---------------------------------------------------------------------------
__global__ __launch_bounds__(256) void kPre(
    const int* __restrict__ head, const int* __restrict__ tail,
    const float* __restrict__ emb, const float* __restrict__ rela,
    const float* __restrict__ fc_w, const float* __restrict__ fc_b)
{
    __shared__ float sX[16][257];
    const int g = blockIdx.x, t = threadIdx.x;
    const int kind = (g < 64) ? 0 : (g < 128 ? 1 : 2);
    const int row0 = ((kind == 0) ? g : (kind == 1) ? (g - 64) : (g - 128)) * 16;

    #pragma unroll 4
    for (int rr = 0; rr < 16; ++rr) {
        const int row = row0 + rr;
        float v;
        if (kind == 0)      v = emb[(size_t)head[row] * DD + t];
        else if (kind == 1) v = emb[(size_t)tail[row] * DD + t];
        else                v = rela[row * DD + t];
        sX[rr][t] = v;
        if (kind == 0)      g_A[row * DD + t] = v;
    }
    __syncthreads();

    const float* Wp = fc_w + (size_t)kind * DD * DD;
    float acc[16];
    #pragma unroll
    for (int r = 0; r < 16; ++r) acc[r] = (kind == 0) ? fc_b[t] : 0.0f;

    #pragma unroll 4
    for (int k = 0; k < DD; ++k) {
        const float wv = Wp[k * DD + t];
        #pragma unroll
        for (int r = 0; r < 16; ++r) acc[r] = fmaf(sX[r][k], wv, acc[r]);
    }

    float* dst = (kind == 0) ? g_AW : (kind == 1) ? g_BW : g_RW;
    #pragma unroll
    for (int r = 0; r < 16; ++r) dst[(row0 + r) * DD + t] = acc[r];

    if (kind != 0) {
        float* dstT = (kind == 1)
            ? (g_BtT + (size_t)(row0 >> 6) * DD * VV + (row0 & 63))
            : (g_relaT + row0);
        #pragma unroll
        for (int it = 0; it < 4; ++it) {
            const int f = it * 256 + t;
            const int d = f >> 2;
            const int q = f & 3;
            float4 v;
            v.x = sX[q * 4 + 0][d];
            v.y = sX[q * 4 + 1][d];
            v.z = sX[q * 4 + 2][d];
            v.w = sX[q * 4 + 3][d];
            *(float4*)&dstT[d * 64 + q * 4] = v;
        }
    }
}

// ---------------------------------------------------------------------------
// Kernel M: fused per (b,i). 1024 blocks x 256 threads.
//   GEMM1 scalar fp32, softmax, GEMM2/GEMM3 n-chunked (64 cols) bf16-split
//   mma with streaming epilogues -> 16-reg accumulators (no spills).
// smem regions (float offsets):
//   A [0, 18432)   : GEMM1 s1h/s2h -> RWH/RWL u32[256][36] -> w1 bufs 2x u32[64][132]
//   sP   [18432)   : [64][68]
//   sPAH [22784), sPAL [25088) : u32[64][36]
//   sAhi [27392), sAlo [35840) : u32[64][132]
//   misc [44288..45376)
// ---------------------------------------------------------------------------
#define SM_S1    0
#define SM_S2    8704
#define SM_RWH   0
#define SM_RWL   9216
#define SM_WB0   0
#define SM_WB1   8448
#define SM_SP    18432
#define SM_PAH   22784
#define SM_PAL   25088
#define SM_AH    27392
#define SM_AL    35840
#define SM_SA    44288
#define SM_SAW   44544
#define SM_SB1   44800
#define SM_SW2   45056
#define SM_SRED  45312
#define SMEM_M_FLOATS 45376
#define SMEM_M_BYTES  (SMEM_M_FLOATS * 4)

// load one w1 n-chunk (64 rows x 128 kpairs, dst stride 132 u32) via cp.async
__device__ __forceinline__ void load_w1_nchunk(uint32_t dst_base, int c, int t)
{
    const uint32_t* src = g_w1bT + (size_t)c * 64 * 128;
    #pragma unroll
    for (int it = 0; it < 8; ++it) {
        const int idx = it * 256 + t;      // 2048 uint4s
        const int n  = idx >> 5;
        const int q4 = (idx & 31) * 4;
        cp_async16(dst_base + (uint32_t)(n * 528 + q4 * 4), src + n * 128 + q4);
    }
}

__global__ __launch_bounds__(256, 1) void kMain(
    const float* __restrict__ att_b1, const float* __restrict__ att_w2,
    const float* __restrict__ att_b2, float* __restrict__ out_ns)
{
    const int t  = threadIdx.x;
    const int b  = blockIdx.x >> 6;
    const int i  = blockIdx.x & 63;
    const int lane = t & 31;
    const int wid  = t >> 5;
    // GEMM1 mapping (4x4 tiles, 16x16 grid)
    const int tx = t & 15, ty = t >> 4;
    const int j0g = ty * 4, r0 = tx * 4;
    // MMA mapping
    const int gid = lane >> 2, tid4 = lane & 3;
    const int wm  = (wid & 3) * 16;       // warp m-tile base
    const int wnl = (wid >> 2) * 32;      // warp n-offset within 64-col chunk

    extern __shared__ float sm[];
    float*    s1h  = sm + SM_S1;
    float*    s2h  = sm + SM_S2;
    uint32_t* sRWH = (uint32_t*)(sm + SM_RWH);   // [256][36]
    uint32_t* sRWL = (uint32_t*)(sm + SM_RWL);
    uint32_t* sWB0 = (uint32_t*)(sm + SM_WB0);   // [64][132]
    uint32_t* sWB1 = (uint32_t*)(sm + SM_WB1);
    float*    sP   = sm + SM_SP;
    uint32_t* sPAH = (uint32_t*)(sm + SM_PAH);   // [64][36]
    uint32_t* sPAL = (uint32_t*)(sm + SM_PAL);
    uint32_t* sAhi = (uint32_t*)(sm + SM_AH);    // [64][132]
    uint32_t* sAlo = (uint32_t*)(sm + SM_AL);
    float*    sA   = sm + SM_SA;
    float*    sAW  = sm + SM_SAW;
    float*    sb1  = sm + SM_SB1;
    float*    sw2  = sm + SM_SW2;
    float*    sred = sm + SM_SRED;

    const int rowA = b * WW + i;
    sA [t] = g_A [rowA * DD + t];
    sAW[t] = g_AW[rowA * DD + t];
    sb1[t] = att_b1[t];
    sw2[t] = att_w2[t];
    __syncthreads();

    // ---- GEMM1: S = H @ rela^T (64x64, K=256 in 2 halves), scalar fp32 ----
    ull c1[4][2];
    #pragma unroll
    for (int u = 0; u < 4; ++u) { c1[u][0] = 0ull; c1[u][1] = 0ull; }

    for (int half = 0; half < 2; ++half) {
        #pragma unroll 2
        for (int it = 0; it < 8; ++it) {
            const int f = it * 256 + t;
            const int d = f >> 4;
            const int c = (f & 15) * 4;
            const int dg = half * 128 + d;
            float4 bv = *(const float4*)&g_BtT[(size_t)b * DD * VV + dg * 64 + c];
            const float sa = sA[dg];
            bv.x *= sa; bv.y *= sa; bv.z *= sa; bv.w *= sa;
            *(float4*)&s1h[d * PAD + c] = bv;
            *(float4*)&s2h[d * PAD + c] = *(const float4*)&g_relaT[dg * 64 + c];
        }
        __syncthreads();

        #pragma unroll 4
        for (int d = 0; d < 128; ++d) {
            const float4 h4 = *(const float4*)&s1h[d * PAD + j0g];
            const ulonglong2 r2 = *(const ulonglong2*)&s2h[d * PAD + r0];
            const ull hp[4] = {pack2(h4.x), pack2(h4.y), pack2(h4.z), pack2(h4.w)};
            #pragma unroll
            for (int u = 0; u < 4; ++u) {
                c1[u][0] = fma2(hp[u], r2.x, c1[u][0]);
                c1[u][1] = fma2(hp[u], r2.y, c1[u][1]);
            }
        }
        __syncthreads();
    }
    #pragma unroll
    for (int u = 0; u < 4; ++u) {
        const float2 lo = unpack2(c1[u][0]);
        const float2 hi = unpack2(c1[u][1]);
        *(float4*)&sP[(j0g + u) * PAD + r0] = make_float4(lo.x, lo.y, hi.x, hi.y);
    }
    __syncthreads();

    // async: RWB hi/lo images (overlaps softmax)
    {
        const uint32_t hB = smem_u32(sRWH);
        const uint32_t lB = smem_u32(sRWL);
        #pragma unroll
        for (int it = 0; it < 8; ++it) {
            const int idx = it * 256 + t;   // 2048 uint4s per image
            const int n  = idx >> 3;
            const int q4 = (idx & 7) * 4;
            cp_async16(hB + (uint32_t)(n * 144 + q4 * 4), g_rwbHi + n * 32 + q4);
            cp_async16(lB + (uint32_t)(n * 144 + q4 * 4), g_rwbLo + n * 32 + q4);
        }
        CP_COMMIT();
    }

    // ---- mask + row softmax over R; pack P hi/lo pairs for GEMM2 ----
    {
        const int j = t >> 2, q = t & 3;
        const float nul = sP[j * PAD + 63];
        float v[16];
        float mx = -1e30f;
        #pragma unroll
        for (int m = 0; m < 16; ++m) {
            float s = sP[j * PAD + q * 16 + m];
            s = (s <= nul) ? -1e10f : s;
            v[m] = s;
            mx = fmaxf(mx, s);
        }
        mx = fmaxf(mx, __shfl_xor_sync(0xffffffffu, mx, 1));
        mx = fmaxf(mx, __shfl_xor_sync(0xffffffffu, mx, 2));
        float se = 0.0f;
        #pragma unroll
        for (int m = 0; m < 16; ++m) { v[m] = expf(v[m] - mx); se += v[m]; }
        se += __shfl_xor_sync(0xffffffffu, se, 1);
        se += __shfl_xor_sync(0xffffffffu, se, 2);
        const float inv = 1.0f / se;
        #pragma unroll
        for (int m = 0; m < 16; ++m) {
            v[m] *= inv;
            sP[j * PAD + q * 16 + m] = v[m];
        }
        #pragma unroll
        for (int mm = 0; mm < 8; ++mm) {
            const float x0 = v[2 * mm], x1 = v[2 * mm + 1];
            sPAH[j * 36 + q * 8 + mm] = pkbf2(x0, x1);
            sPAL[j * 36 + q * 8 + mm] = pkbf2(x0 - bf16hi_f(x0), x1 - bf16hi_f(x1));
        }
    }
    __syncthreads();

    // write norm_scores
    const size_t ns_base = ((size_t)(b * NN + i * VV)) * RR;
    #pragma unroll
    for (int it = 0; it < 16; ++it) {
        const int l = it * 256 + t;
        const int j = l >> 6, r = l & 63;
        out_ns[ns_base + (size_t)j * RR + r] = sP[j * PAD + r];
    }
    CP_WAIT0();
    __syncthreads();

    // ---- GEMM2: PV = P @ RW, n-chunked (4 x 64 cols), bf16-split 3-pass ----
    const int pr0 = (wm + gid) * 36;
    const int pr1 = (wm + gid + 8) * 36;
    const int row0 = wm + gid, row1 = wm + gid + 8;
    const size_t tvb0 = ((size_t)(b * NN + i * VV + row0)) * DD;
    const size_t tvb1 = ((size_t)(b * NN + i * VV + row1)) * DD;
    const float* bwr0 = g_BW + (size_t)(b * VV + row0) * DD;
    const float* bwr1 = g_BW + (size_t)(b * VV + row1) * DD;
    uint32_t* tvu = (uint32_t*)g_tvh;

    for (int c = 0; c < 4; ++c) {
        float a2[4][4];
        #pragma unroll
        for (int nt = 0; nt < 4; ++nt)
            #pragma unroll
            for (int e = 0; e < 4; ++e) a2[nt][e] = 0.0f;

        #pragma unroll
        for (int ks = 0; ks < 4; ++ks) {
            const int gp = ks * 8 + tid4;
            const uint32_t h0 = sPAH[pr0 + gp],     l0 = sPAL[pr0 + gp];
            const uint32_t h1 = sPAH[pr1 + gp],     l1 = sPAL[pr1 + gp];
            const uint32_t h2 = sPAH[pr0 + gp + 4], l2 = sPAL[pr0 + gp + 4];
            const uint32_t h3 = sPAH[pr1 + gp + 4], l3 = sPAL[pr1 + gp + 4];
            #pragma unroll
            for (int nt = 0; nt < 4; ++nt) {
                const int n = c * 64 + wnl + nt * 8 + gid;
                const uint32_t bh0 = sRWH[n * 36 + gp];
                const uint32_t bh1 = sRWH[n * 36 + gp + 4];
                const uint32_t bl0 = sRWL[n * 36 + gp];
                const uint32_t bl1 = sRWL[n * 36 + gp + 4];
                mma_bf16(a2[nt], h0, h1, h2, h3, bh0, bh1);
                mma_bf16(a2[nt], l0, l1, l2, l3, bh0, bh1);
                mma_bf16(a2[nt], h0, h1, h2, h3, bl0, bl1);
            }
        }

        if (c == 3) {
            // all RW reads done chip-wide -> region A reusable for w1 bufs
            __syncthreads();
            load_w1_nchunk(smem_u32(sWB0), 0, t);
            CP_COMMIT();
            load_w1_nchunk(smem_u32(sWB1), 1, t);
            CP_COMMIT();
        }

        // tv epilogue for this chunk -> g_tvh + sAhi/sAlo
        #pragma unroll
        for (int nt = 0; nt < 4; ++nt) {
            const int col = c * 64 + wnl + nt * 8 + 2 * tid4;
            const float aw0 = sAW[col], aw1v = sAW[col + 1];
            const float2 bw0 = *(const float2*)(bwr0 + col);
            const float2 bw1 = *(const float2*)(bwr1 + col);
            const float t00 = tanh_fast(a2[nt][0] + aw0  + bw0.x);
            const float t01 = tanh_fast(a2[nt][1] + aw1v + bw0.y);
            const float t10 = tanh_fast(a2[nt][2] + aw0  + bw1.x);
            const float t11 = tanh_fast(a2[nt][3] + aw1v + bw1.y);
            tvu[(tvb0 + col) >> 1] = pkbf2(t00, t01);
            tvu[(tvb1 + col) >> 1] = pkbf2(t10, t11);
            const int p = col >> 1;
            sAhi[row0 * 132 + p] = pkbf2(t00, t01);
            sAlo[row0 * 132 + p] = pkbf2(t00 - bf16hi_f(t00), t01 - bf16hi_f(t01));
            sAhi[row1 * 132 + p] = pkbf2(t10, t11);
            sAlo[row1 * 132 + p] = pkbf2(t10 - bf16hi_f(t10), t11 - bf16hi_f(t11));
        }
    }
    __syncthreads();
    CP_WAIT1();   // w1 chunk 0 ready

    // ---- GEMM3: Hid = tv @ w1, n-chunked (4 x 64 cols), split-A 2-pass,
    //      streaming att epilogue (no hid materialization) ----
    const int ar0 = (wm + gid) * 132;
    const int ar1 = (wm + gid + 8) * 132;
    float p0 = 0.0f, p1 = 0.0f;

    for (int c = 0; c < 4; ++c) {
        const uint32_t* wb = (c & 1) ? sWB1 : sWB0;
        float a3[4][4];
        #pragma unroll
        for (int nt = 0; nt < 4; ++nt)
            #pragma unroll
            for (int e = 0; e < 4; ++e) a3[nt][e] = 0.0f;

        #pragma unroll 4
        for (int ks = 0; ks < 16; ++ks) {
            const int gp = ks * 8 + tid4;
            const uint32_t h0 = sAhi[ar0 + gp],     l0 = sAlo[ar0 + gp];
            const uint32_t h1 = sAhi[ar1 + gp],     l1 = sAlo[ar1 + gp];
            const uint32_t h2 = sAhi[ar0 + gp + 4], l2 = sAlo[ar0 + gp + 4];
            const uint32_t h3 = sAhi[ar1 + gp + 4], l3 = sAlo[ar1 + gp + 4];
            #pragma unroll
            for (int nt = 0; nt < 4; ++nt) {
                const int nl = wnl + nt * 8 + gid;
                const uint32_t b0 = wb[nl * 132 + gp];
                const uint32_t b1 = wb[nl * 132 + gp + 4];
                mma_bf16(a3[nt], h0, h1, h2, h3, b0, b1);
                mma_bf16(a3[nt], l0, l1, l2, l3, b0, b1);
            }
        }

        // epilogue: accumulate att partial sums for this chunk
        #pragma unroll
        for (int nt = 0; nt < 4; ++nt) {
            const int col = c * 64 + wnl + nt * 8 + 2 * tid4;
            p0 = fmaf(tanh_fast(a3[nt][0] + sb1[col]),     sw2[col],     p0);
            p0 = fmaf(tanh_fast(a3[nt][1] + sb1[col + 1]), sw2[col + 1], p0);
            p1 = fmaf(tanh_fast(a3[nt][2] + sb1[col]),     sw2[col],     p1);
            p1 = fmaf(tanh_fast(a3[nt][3] + sb1[col + 1]), sw2[col + 1], p1);
        }

        // prefetch pipeline: at c issue chunk c+2 into the buffer c used
        if (c < 2) {
            __syncthreads();                    // all warps done reading wb
            load_w1_nchunk(smem_u32((c & 1) ? sWB1 : sWB0), c + 2, t);
            CP_COMMIT();
            CP_WAIT1();                         // next chunk (c+1) ready
        } else if (c == 2) {
            CP_WAIT0();                         // chunk 3 ready
        }
    }

    // ---- reduce att partial sums ----
    p0 += __shfl_xor_sync(0xffffffffu, p0, 1);
    p0 += __shfl_xor_sync(0xffffffffu, p0, 2);
    p1 += __shfl_xor_sync(0xffffffffu, p1, 1);
    p1 += __shfl_xor_sync(0xffffffffu, p1, 2);

    if (wid < 4) {
        if (tid4 == 0) { sred[wm + gid] = p0; sred[wm + gid + 8] = p1; }
    }
    __syncthreads();
    if (wid >= 4) {
        if (tid4 == 0) { sred[wm + gid] += p0; sred[wm + gid + 8] += p1; }
    }
    __syncthreads();
    if (t < 64)
        g_att[b * NN + i * VV + t] = sred[t] + att_b2[0];
}

// ---------------------------------------------------------------------------
// Kernel F1: softmax over N of att per batch; writes att_norms; zeroes g_fuse
// ---------------------------------------------------------------------------
__global__ __launch_bounds__(256) void kAtt(float* __restrict__ out_attn)
{
    const int b = blockIdx.x, t = threadIdx.x;
    __shared__ float red[8];
    float vals[16];
    float mx = -1e30f;
    #pragma unroll
    for (int it = 0; it < 16; ++it) {
        vals[it] = g_att[b * NN + it * 256 + t];
        mx = fmaxf(mx, vals[it]);
    }
    #pragma unroll
    for (int o = 16; o; o >>= 1) mx = fmaxf(mx, __shfl_xor_sync(0xffffffffu, mx, o));
    if ((t & 31) == 0) red[t >> 5] = mx;
    __syncthreads();
    float bm = red[0];
    #pragma unroll
    for (int w = 1; w < 8; ++w) bm = fmaxf(bm, red[w]);
    __syncthreads();

    float s = 0.0f;
    #pragma unroll
    for (int it = 0; it < 16; ++it) { vals[it] = expf(vals[it] - bm); s += vals[it]; }
    #pragma unroll
    for (int o = 16; o; o >>= 1) s += __shfl_xor_sync(0xffffffffu, s, o);
    if ((t & 31) == 0) red[t >> 5] = s;
    __syncthreads();
    float bs = 0.0f;
    #pragma unroll
    for (int w = 0; w < 8; ++w) bs += red[w];
    const float inv = 1.0f / bs;
    #pragma unroll
    for (int it = 0; it < 16; ++it)
        out_attn[b * NN + it * 256 + t] = vals[it] * inv;
    g_fuse[b * DD + t] = 0.0f;
}

// ---------------------------------------------------------------------------
// Kernel F2: fuse = sum_n att_norms[n] * tv[n,:]  (1024 blocks, bf16 tv)
// ---------------------------------------------------------------------------
__global__ __launch_bounds__(256) void kFuse(const float* __restrict__ attn)
{
    const int b = blockIdx.x >> 6, ch = blockIdx.x & 63, t = threadIdx.x;
    __shared__ float sa[64];
    const int n0 = ch * 64;
    if (t < 64) sa[t] = attn[b * NN + n0 + t];
    __syncthreads();

    const __nv_bfloat16* tvp = g_tvh + ((size_t)(b * NN + n0)) * DD + t;
    float a0 = 0, a1 = 0, a2 = 0, a3 = 0, a4 = 0, a5 = 0, a6 = 0, a7 = 0;
    #pragma unroll
    for (int n = 0; n < 64; n += 8) {
        a0 = fmaf(sa[n + 0], __bfloat162float(tvp[(size_t)(n + 0) * DD]), a0);
        a1 = fmaf(sa[n + 1], __bfloat162float(tvp[(size_t)(n + 1) * DD]), a1);
        a2 = fmaf(sa[n + 2], __bfloat162float(tvp[(size_t)(n + 2) * DD]), a2);
        a3 = fmaf(sa[n + 3], __bfloat162float(tvp[(size_t)(n + 3) * DD]), a3);
        a4 = fmaf(sa[n + 4], __bfloat162float(tvp[(size_t)(n + 4) * DD]), a4);
        a5 = fmaf(sa[n + 5], __bfloat162float(tvp[(size_t)(n + 5) * DD]), a5);
        a6 = fmaf(sa[n + 6], __bfloat162float(tvp[(size_t)(n + 6) * DD]), a6);
        a7 = fmaf(sa[n + 7], __bfloat162float(tvp[(size_t)(n + 7) * DD]), a7);
    }
    atomicAdd(&g_fuse[b * DD + t], ((a0 + a1) + (a2 + a3)) + ((a4 + a5) + (a6 + a7)));
}

// ---------------------------------------------------------------------------
// Kernel F3: logits[b] = fuse . out_w + out_b
// ---------------------------------------------------------------------------
__global__ __launch_bounds__(256) void kLogits(
    float* __restrict__ out, const float* __restrict__ ow, const float* __restrict__ ob)
{
    const int b = blockIdx.x, t = threadIdx.x;
    __shared__ float red[8];
    float v = g_fuse[b * DD + t] * ow[t];
    #pragma unroll
    for (int o = 16; o; o >>= 1) v += __shfl_xor_sync(0xffffffffu, v, o);
    if ((t & 31) == 0) red[t >> 5] = v;
    __syncthreads();
    if (t == 0) {
        float s = 0.0f;
        #pragma unroll
        for (int w = 0; w < 8; ++w) s += red[w];
        out[b] = s + ob[0];
    }
}

// ---------------------------------------------------------------------------
// Launch
// ---------------------------------------------------------------------------
extern "C" void kernel_launch(void* const* d_in, const int* in_sizes, int n_in,
                              void* d_out, int out_size)
{
    const int*   head = (const int*)d_in[0];
    const int*   tail = (const int*)d_in[1];
    const float* emb  = (const float*)d_in[2];
    const float* rela = (const float*)d_in[3];
    const float* fc_w = (const float*)d_in[4];
    const float* fc_b = (const float*)d_in[5];
    const float* aw1  = (const float*)d_in[6];
    const float* ab1  = (const float*)d_in[7];
    const float* aw2  = (const float*)d_in[8];
    const float* ab2  = (const float*)d_in[9];
    const float* ow   = (const float*)d_in[10];
    const float* ob   = (const float*)d_in[11];

    float* out        = (float*)d_out;
    float* out_logits = out;
    float* out_attn   = out + BB;
    float* out_ns     = out + BB + BB * NN;

    cudaFuncSetAttribute(kMain, cudaFuncAttributeMaxDynamicSharedMemorySize, SMEM_M_BYTES);

    kPre   <<<132,   256>>>(head, tail, emb, rela, fc_w, fc_b);
    kW1T   <<<128,   256>>>(aw1);
    kRWT   <<<32,    256>>>();
    kMain  <<<BB*WW, 256, SMEM_M_BYTES>>>(ab1, aw2, ab2, out_ns);
    kAtt   <<<BB,    256>>>(out_attn);
    kFuse  <<<BB*64, 256>>>(out_attn);
    kLogits<<<BB,    256>>>(out_logits, ow, ob);
}

// round 12
// speedup vs baseline: 1.1960x; 1.1960x over previous
#include <cuda_runtime.h>
#include <cuda_bf16.h>
#include <cstdint>
#include <cstddef>

#define BB   16
#define WW   64
#define VV   64
#define DD   256
#define RR   64
#define NN   (WW*VV)
#define PAD  68

typedef unsigned long long ull;

__device__ float g_A   [BB*WW*DD];
__device__ float g_BtT [BB*DD*VV];
__device__ float g_relaT[DD*RR];
__device__ float g_AW  [BB*WW*DD];
__device__ float g_BW  [BB*VV*DD];
__device__ float g_RW  [RR*DD];
__device__ uint32_t g_w1bT [DD*DD/2];
__device__ uint32_t g_rwbHi[DD*RR/2];
__device__ uint32_t g_rwbLo[DD*RR/2];
__device__ __nv_bfloat16 g_tvh[(size_t)BB*NN*DD];
__device__ float g_att [BB*NN];
__device__ float g_fuse[BB*DD];

__device__ __forceinline__ float tanh_fast(float x) {
    float y; asm("tanh.approx.f32 %0, %1;" : "=f"(y) : "f"(x)); return y;
}
__device__ __forceinline__ ull fma2(ull a, ull b, ull c) {
    ull d; asm("fma.rn.f32x2 %0, %1, %2, %3;" : "=l"(d) : "l"(a), "l"(b), "l"(c)); return d;
}
__device__ __forceinline__ ull pack2(float x) {
    ull r; asm("mov.b64 %0, {%1, %1};" : "=l"(r) : "f"(x)); return r;
}
__device__ __forceinline__ float2 unpack2(ull v) {
    float2 f; asm("mov.b64 {%0, %1}, %2;" : "=f"(f.x), "=f"(f.y) : "l"(v)); return f;
}
__device__ __forceinline__ uint32_t smem_u32(const void* p) {
    uint32_t a;
    asm("{ .reg .u64 tmp; cvta.to.shared.u64 tmp, %1; cvt.u32.u64 %0, tmp; }" : "=r"(a) : "l"(p));
    return a;
}
__device__ __forceinline__ void cp_async16(uint32_t daddr, const void* src) {
    asm volatile("cp.async.cg.shared.global [%0], [%1], 16;" :: "r"(daddr), "l"(src) : "memory");
}
#define CP_COMMIT() asm volatile("cp.async.commit_group;" ::: "memory")
#define CP_WAIT0()  asm volatile("cp.async.wait_group 0;" ::: "memory")
#define CP_WAIT1()  asm volatile("cp.async.wait_group 1;" ::: "memory")

__device__ __forceinline__ void mma_bf16(float c[4],
    uint32_t a0, uint32_t a1, uint32_t a2, uint32_t a3, uint32_t b0, uint32_t b1)
{
    asm volatile(
        "mma.sync.aligned.m16n8k16.row.col.f32.bf16.bf16.f32 "
        "{%0,%1,%2,%3}, {%4,%5,%6,%7}, {%8,%9}, {%0,%1,%2,%3};"
        : "+f"(c[0]), "+f"(c[1]), "+f"(c[2]), "+f"(c[3])
        : "r"(a0), "r"(a1), "r"(a2), "r"(a3), "r"(b0), "r"(b1));
}
__device__ __forceinline__ uint32_t pkbf2(float a, float b) {
    return (uint32_t)__bfloat16_as_ushort(__float2bfloat16_rn(a))
         | ((uint32_t)__bfloat16_as_ushort(__float2bfloat16_rn(b)) << 16);
}
__device__ __forceinline__ float bf16hi_f(float x) {
    return __bfloat162float(__float2bfloat16_rn(x));
}

__global__ __launch_bounds__(256) void kW1T(const float* __restrict__ aw1)
{
    const int p = blockIdx.x, n = threadIdx.x;
    g_w1bT[n * 128 + p] = pkbf2(aw1[(2 * p) * DD + n], aw1[(2 * p + 1) * DD + n]);
}

__global__ __launch_bounds__(256) void kRWT()
{
    const int p = blockIdx.x, n = threadIdx.x;
    const float a = g_RW[(2 * p) * DD + n];
    const float b = g_RW[(2 * p + 1) * DD + n];
    g_rwbHi[n * 32 + p] = pkbf2(a, b);
    g_rwbLo[n * 32 + p] = pkbf2(a - bf16hi_f(a), b - bf16hi_f(b));
}

__global__ __launch_bounds__(256) void kPre(
    const int* __restrict__ head, const int* __restrict__ tail,
    const float* __restrict__ emb, const float* __restrict__ rela,
    const float* __restrict__ fc_w, const float* __restrict__ fc_b)
{
    __shared__ float sX[16][257];
    const int g = blockIdx.x, t = threadIdx.x;
    const int kind = (g < 64) ? 0 : (g < 128 ? 1 : 2);
    const int row0 = ((kind == 0) ? g : (kind == 1) ? (g - 64) : (g - 128)) * 16;

    #pragma unroll 4
    for (int rr = 0; rr < 16; ++rr) {
        const int row = row0 + rr;
        float v;
        if (kind == 0)      v = emb[(size_t)head[row] * DD + t];
        else if (kind == 1) v = emb[(size_t)tail[row] * DD + t];
        else                v = rela[row * DD + t];
        sX[rr][t] = v;
        if (kind == 0) g_A[row * DD + t] = v;
    }
    __syncthreads();

    const float* Wp = fc_w + (size_t)kind * DD * DD;
    float acc[16];
    #pragma unroll
    for (int r = 0; r < 16; ++r) acc[r] = (kind == 0) ? fc_b[t] : 0.0f;
    #pragma unroll 4
    for (int k = 0; k < DD; ++k) {
        const float wv = Wp[k * DD + t];
        #pragma unroll
        for (int r = 0; r < 16; ++r) acc[r] = fmaf(sX[r][k], wv, acc[r]);
    }
    float* dst = (kind == 0) ? g_AW : (kind == 1) ? g_BW : g_RW;
    #pragma unroll
    for (int r = 0; r < 16; ++r) dst[(row0 + r) * DD + t] = acc[r];

    if (kind != 0) {
        float* dstT = (kind == 1)
            ? (g_BtT + (size_t)(row0 >> 6) * DD * VV + (row0 & 63))
            : (g_relaT + row0);
        #pragma unroll
        for (int it = 0; it < 4; ++it) {
            const int f = it * 256 + t;
            const int d = f >> 2, q = f & 3;
            float4 v;
            v.x = sX[q * 4 + 0][d]; v.y = sX[q * 4 + 1][d];
            v.z = sX[q * 4 + 2][d]; v.w = sX[q * 4 + 3][d];
            *(float4*)&dstT[d * 64 + q * 4] = v;
        }
    }
}

// ---------------------------------------------------------------------------
// kMain: 1024 blocks x 256, 2 CTAs/SM (smem 110848 B, regs <=128).
// RA region (9216 floats) reused: GEMM1 tiles -> RW slices -> w1 chunks.
// ---------------------------------------------------------------------------
#define SM_RA    0
#define SM_SP    9216
#define SM_PAH   13568
#define SM_PAL   15872
#define SM_AH    18176
#define SM_SA    26624
#define SM_SAW   26880
#define SM_SB1   27136
#define SM_SW2   27392
#define SM_SRED  27648
#define SMEM_M_FLOATS 27712
#define SMEM_M_BYTES  (SMEM_M_FLOATS * 4)

__global__ __launch_bounds__(256, 2) void kMain(
    const float* __restrict__ att_b1, const float* __restrict__ att_w2,
    const float* __restrict__ att_b2, float* __restrict__ out_ns)
{
    const int t  = threadIdx.x;
    const int b  = blockIdx.x >> 6;
    const int i  = blockIdx.x & 63;
    const int lane = t & 31, wid = t >> 5;
    const int tx = t & 15, ty = t >> 4;
    const int j0g = ty * 4, r0 = tx * 4;
    const int gid = lane >> 2, tid4 = lane & 3;
    const int wm  = (wid & 3) * 16;
    const int wnl = (wid >> 2) * 32;

    extern __shared__ float sm[];
    float*    sRA  = sm + SM_RA;
    float*    sP   = sm + SM_SP;
    uint32_t* sPAH = (uint32_t*)(sm + SM_PAH);
    uint32_t* sPAL = (uint32_t*)(sm + SM_PAL);
    uint32_t* sAhi = (uint32_t*)(sm + SM_AH);    // [64][132]
    float*    sA   = sm + SM_SA;
    float*    sAW  = sm + SM_SAW;
    float*    sb1  = sm + SM_SB1;
    float*    sw2  = sm + SM_SW2;
    float*    sred = sm + SM_SRED;

    const int rowA = b * WW + i;
    sA [t] = g_A [rowA * DD + t];
    sAW[t] = g_AW[rowA * DD + t];
    sb1[t] = att_b1[t];
    sw2[t] = att_w2[t];
    __syncthreads();

    // ---- GEMM1: scalar fp32, 4 k-chunks of 64, single-buffered ----
    const float* btT = g_BtT + (size_t)b * DD * VV;
    float* s1h = sRA;            // [64][68]
    float* s2h = sRA + 4352;     // [64][68]
    ull c1[4][2];
    #pragma unroll
    for (int u = 0; u < 4; ++u) { c1[u][0] = 0ull; c1[u][1] = 0ull; }

    for (int kc = 0; kc < 4; ++kc) {
        #pragma unroll
        for (int it = 0; it < 4; ++it) {
            const int f = it * 256 + t;       // 1024 float4 per tile
            const int d = f >> 4;
            const int c = (f & 15) * 4;
            const int dg = kc * 64 + d;
            float4 bv = *(const float4*)(btT + dg * 64 + c);
            const float sa = sA[dg];
            bv.x *= sa; bv.y *= sa; bv.z *= sa; bv.w *= sa;
            *(float4*)&s1h[d * PAD + c] = bv;
            *(float4*)&s2h[d * PAD + c] = *(const float4*)&g_relaT[dg * 64 + c];
        }
        __syncthreads();
        #pragma unroll 4
        for (int d = 0; d < 64; ++d) {
            const float4 h4 = *(const float4*)&s1h[d * PAD + j0g];
            const ulonglong2 r2 = *(const ulonglong2*)&s2h[d * PAD + r0];
            const ull hp[4] = {pack2(h4.x), pack2(h4.y), pack2(h4.z), pack2(h4.w)};
            #pragma unroll
            for (int u = 0; u < 4; ++u) {
                c1[u][0] = fma2(hp[u], r2.x, c1[u][0]);
                c1[u][1] = fma2(hp[u], r2.y, c1[u][1]);
            }
        }
        __syncthreads();
    }
    #pragma unroll
    for (int u = 0; u < 4; ++u) {
        const float2 lo = unpack2(c1[u][0]);
        const float2 hi = unpack2(c1[u][1]);
        *(float4*)&sP[(j0g + u) * PAD + r0] = make_float4(lo.x, lo.y, hi.x, hi.y);
    }
    __syncthreads();

    // RW slice prologue: slices 0,1 (each hi[64][36]+lo[64][36] u32)
    uint32_t* rwBuf[2] = { (uint32_t*)sRA, (uint32_t*)sRA + 4608 };
    #pragma unroll
    for (int s = 0; s < 2; ++s) {
        const uint32_t hB = smem_u32(rwBuf[s]);
        const uint32_t lB = smem_u32(rwBuf[s] + 2304);
        #pragma unroll
        for (int it = 0; it < 2; ++it) {
            const int idx = it * 256 + t;       // 512 uint4 per image
            const int n  = idx >> 3;
            const int q4 = (idx & 7) * 4;
            cp_async16(hB + (uint32_t)(n * 144 + q4 * 4), g_rwbHi + (s * 64 + n) * 32 + q4);
            cp_async16(lB + (uint32_t)(n * 144 + q4 * 4), g_rwbLo + (s * 64 + n) * 32 + q4);
        }
        CP_COMMIT();
    }

    // ---- softmax + pack P hi/lo ----
    {
        const int j = t >> 2, q = t & 3;
        const float nul = sP[j * PAD + 63];
        float v[16];
        float mx = -1e30f;
        #pragma unroll
        for (int m = 0; m < 16; ++m) {
            float s = sP[j * PAD + q * 16 + m];
            s = (s <= nul) ? -1e10f : s;
            v[m] = s;
            mx = fmaxf(mx, s);
        }
        mx = fmaxf(mx, __shfl_xor_sync(0xffffffffu, mx, 1));
        mx = fmaxf(mx, __shfl_xor_sync(0xffffffffu, mx, 2));
        float se = 0.0f;
        #pragma unroll
        for (int m = 0; m < 16; ++m) { v[m] = expf(v[m] - mx); se += v[m]; }
        se += __shfl_xor_sync(0xffffffffu, se, 1);
        se += __shfl_xor_sync(0xffffffffu, se, 2);
        const float inv = 1.0f / se;
        #pragma unroll
        for (int m = 0; m < 16; ++m) { v[m] *= inv; sP[j * PAD + q * 16 + m] = v[m]; }
        #pragma unroll
        for (int mm = 0; mm < 8; ++mm) {
            const float x0 = v[2 * mm], x1 = v[2 * mm + 1];
            sPAH[j * 36 + q * 8 + mm] = pkbf2(x0, x1);
            sPAL[j * 36 + q * 8 + mm] = pkbf2(x0 - bf16hi_f(x0), x1 - bf16hi_f(x1));
        }
    }
    __syncthreads();

    const size_t ns_base = ((size_t)(b * NN + i * VV)) * RR;
    #pragma unroll
    for (int it = 0; it < 16; ++it) {
        const int l = it * 256 + t;
        out_ns[ns_base + (size_t)(l >> 6) * RR + (l & 63)] = sP[(l >> 6) * PAD + (l & 63)];
    }

    // ---- GEMM2: 4 n-chunks of 64 cols, bf16-split 3-pass ----
    const int pr0 = (wm + gid) * 36;
    const int pr1 = (wm + gid + 8) * 36;
    const int row0 = wm + gid, row1 = wm + gid + 8;
    const size_t tvb0 = ((size_t)(b * NN + i * VV + row0)) * DD;
    const size_t tvb1 = ((size_t)(b * NN + i * VV + row1)) * DD;
    const float* bwr0 = g_BW + (size_t)(b * VV + row0) * DD;
    const float* bwr1 = g_BW + (size_t)(b * VV + row1) * DD;
    uint32_t* tvu = (uint32_t*)g_tvh;

    for (int c = 0; c < 4; ++c) {
        if (c == 3) { CP_WAIT0(); } else { CP_WAIT1(); }
        __syncthreads();
        const uint32_t* rwH = rwBuf[c & 1];
        const uint32_t* rwL = rwH + 2304;

        float a2[4][4];
        #pragma unroll
        for (int nt = 0; nt < 4; ++nt)
            #pragma unroll
            for (int e = 0; e < 4; ++e) a2[nt][e] = 0.0f;

        #pragma unroll
        for (int ks = 0; ks < 4; ++ks) {
            const int gp = ks * 8 + tid4;
            const uint32_t h0 = sPAH[pr0 + gp],     l0 = sPAL[pr0 + gp];
            const uint32_t h1 = sPAH[pr1 + gp],     l1 = sPAL[pr1 + gp];
            const uint32_t h2 = sPAH[pr0 + gp + 4], l2 = sPAL[pr0 + gp + 4];
            const uint32_t h3 = sPAH[pr1 + gp + 4], l3 = sPAL[pr1 + gp + 4];
            #pragma unroll
            for (int nt = 0; nt < 4; ++nt) {
                const int nl = wnl + nt * 8 + gid;
                const uint32_t bh0 = rwH[nl * 36 + gp];
                const uint32_t bh1 = rwH[nl * 36 + gp + 4];
                const uint32_t bl0 = rwL[nl * 36 + gp];
                const uint32_t bl1 = rwL[nl * 36 + gp + 4];
                mma_bf16(a2[nt], h0, h1, h2, h3, bh0, bh1);
                mma_bf16(a2[nt], l0, l1, l2, l3, bh0, bh1);
                mma_bf16(a2[nt], h0, h1, h2, h3, bl0, bl1);
            }
        }
        __syncthreads();   // done reading rwBuf[c&1]

        if (c + 2 < 4) {
            const uint32_t hB = smem_u32(rwBuf[c & 1]);
            const uint32_t lB = smem_u32(rwBuf[c & 1] + 2304);
            #pragma unroll
            for (int it = 0; it < 2; ++it) {
                const int idx = it * 256 + t;
                const int n  = idx >> 3;
                const int q4 = (idx & 7) * 4;
                cp_async16(hB + (uint32_t)(n * 144 + q4 * 4), g_rwbHi + ((c + 2) * 64 + n) * 32 + q4);
                cp_async16(lB + (uint32_t)(n * 144 + q4 * 4), g_rwbLo + ((c + 2) * 64 + n) * 32 + q4);
            }
            CP_COMMIT();
        }

        // tv epilogue -> g_tvh + sAhi (bf16 hi only)
        #pragma unroll
        for (int nt = 0; nt < 4; ++nt) {
            const int col = c * 64 + wnl + nt * 8 + 2 * tid4;
            const float aw0 = sAW[col], aw1v = sAW[col + 1];
            const float2 bw0 = *(const float2*)(bwr0 + col);
            const float2 bw1 = *(const float2*)(bwr1 + col);
            const float t00 = tanh_fast(a2[nt][0] + aw0  + bw0.x);
            const float t01 = tanh_fast(a2[nt][1] + aw1v + bw0.y);
            const float t10 = tanh_fast(a2[nt][2] + aw0  + bw1.x);
            const float t11 = tanh_fast(a2[nt][3] + aw1v + bw1.y);
            const uint32_t u0 = pkbf2(t00, t01), u1 = pkbf2(t10, t11);
            tvu[(tvb0 + col) >> 1] = u0;
            tvu[(tvb1 + col) >> 1] = u1;
            sAhi[row0 * 132 + (col >> 1)] = u0;
            sAhi[row1 * 132 + (col >> 1)] = u1;
        }
    }
    __syncthreads();   // sAhi complete; rwBufs free

    // w1 chunk 0 fill (single buffer [64][132] u32 in RA)
    {
        const uint32_t wB = smem_u32(sRA);
        #pragma unroll
        for (int it = 0; it < 8; ++it) {
            const int idx = it * 256 + t;       // 2048 uint4
            const int n  = idx >> 5;
            const int q4 = (idx & 31) * 4;
            cp_async16(wB + (uint32_t)(n * 528 + q4 * 4), g_w1bT + n * 128 + q4);
        }
        CP_COMMIT();
    }

    // ---- GEMM3: 4 n-chunks of 64 cols, A = bf16-hi only ----
    const int ar0 = (wm + gid) * 132;
    const int ar1 = (wm + gid + 8) * 132;
    const uint32_t* wb = (const uint32_t*)sRA;
    float p0 = 0.0f, p1 = 0.0f;

    for (int c = 0; c < 4; ++c) {
        CP_WAIT0();
        __syncthreads();

        float a3[4][4];
        #pragma unroll
        for (int nt = 0; nt < 4; ++nt)
            #pragma unroll
            for (int e = 0; e < 4; ++e) a3[nt][e] = 0.0f;

        #pragma unroll 4
        for (int ks = 0; ks < 16; ++ks) {
            const int gp = ks * 8 + tid4;
            const uint32_t h0 = sAhi[ar0 + gp];
            const uint32_t h1 = sAhi[ar1 + gp];
            const uint32_t h2 = sAhi[ar0 + gp + 4];
            const uint32_t h3 = sAhi[ar1 + gp + 4];
            #pragma unroll
            for (int nt = 0; nt < 4; ++nt) {
                const int nl = wnl + nt * 8 + gid;
                mma_bf16(a3[nt], h0, h1, h2, h3, wb[nl * 132 + gp], wb[nl * 132 + gp + 4]);
            }
        }
        __syncthreads();   // done reading w1 buffer

        if (c < 3) {
            const uint32_t wB = smem_u32(sRA);
            #pragma unroll
            for (int it = 0; it < 8; ++it) {
                const int idx = it * 256 + t;
                const int n  = idx >> 5;
                const int q4 = (idx & 31) * 4;
                cp_async16(wB + (uint32_t)(n * 528 + q4 * 4),
                           g_w1bT + (size_t)((c + 1) * 64 + n) * 128 + q4);
            }
            CP_COMMIT();
        }

        #pragma unroll
        for (int nt = 0; nt < 4; ++nt) {
            const int col = c * 64 + wnl + nt * 8 + 2 * tid4;
            p0 = fmaf(tanh_fast(a3[nt][0] + sb1[col]),     sw2[col],     p0);
            p0 = fmaf(tanh_fast(a3[nt][1] + sb1[col + 1]), sw2[col + 1], p0);
            p1 = fmaf(tanh_fast(a3[nt][2] + sb1[col]),     sw2[col],     p1);
            p1 = fmaf(tanh_fast(a3[nt][3] + sb1[col + 1]), sw2[col + 1], p1);
        }
    }

    // ---- reduce att partial sums ----
    p0 += __shfl_xor_sync(0xffffffffu, p0, 1);
    p0 += __shfl_xor_sync(0xffffffffu, p0, 2);
    p1 += __shfl_xor_sync(0xffffffffu, p1, 1);
    p1 += __shfl_xor_sync(0xffffffffu, p1, 2);

    if (wid < 4) {
        if (tid4 == 0) { sred[wm + gid] = p0; sred[wm + gid + 8] = p1; }
    }
    __syncthreads();
    if (wid >= 4) {
        if (tid4 == 0) { sred[wm + gid] += p0; sred[wm + gid + 8] += p1; }
    }
    __syncthreads();
    if (t < 64)
        g_att[b * NN + i * VV + t] = sred[t] + att_b2[0];
}

__global__ __launch_bounds__(256) void kAtt(float* __restrict__ out_attn)
{
    const int b = blockIdx.x, t = threadIdx.x;
    __shared__ float red[8];
    float vals[16];
    float mx = -1e30f;
    #pragma unroll
    for (int it = 0; it < 16; ++it) {
        vals[it] = g_att[b * NN + it * 256 + t];
        mx = fmaxf(mx, vals[it]);
    }
    #pragma unroll
    for (int o = 16; o; o >>= 1) mx = fmaxf(mx, __shfl_xor_sync(0xffffffffu, mx, o));
    if ((t & 31) == 0) red[t >> 5] = mx;
    __syncthreads();
    float bm = red[0];
    #pragma unroll
    for (int w = 1; w < 8; ++w) bm = fmaxf(bm, red[w]);
    __syncthreads();
    float s = 0.0f;
    #pragma unroll
    for (int it = 0; it < 16; ++it) { vals[it] = expf(vals[it] - bm); s += vals[it]; }
    #pragma unroll
    for (int o = 16; o; o >>= 1) s += __shfl_xor_sync(0xffffffffu, s, o);
    if ((t & 31) == 0) red[t >> 5] = s;
    __syncthreads();
    float bs = 0.0f;
    #pragma unroll
    for (int w = 0; w < 8; ++w) bs += red[w];
    const float inv = 1.0f / bs;
    #pragma unroll
    for (int it = 0; it < 16; ++it)
        out_attn[b * NN + it * 256 + t] = vals[it] * inv;
    g_fuse[b * DD + t] = 0.0f;
}

__global__ __launch_bounds__(256) void kFuse(const float* __restrict__ attn)
{
    const int b = blockIdx.x >> 6, ch = blockIdx.x & 63, t = threadIdx.x;
    __shared__ float sa[64];
    const int n0 = ch * 64;
    if (t < 64) sa[t] = attn[b * NN + n0 + t];
    __syncthreads();

    const __nv_bfloat16* tvp = g_tvh + ((size_t)(b * NN + n0)) * DD + t;
    float a0 = 0, a1 = 0, a2 = 0, a3 = 0, a4 = 0, a5 = 0, a6 = 0, a7 = 0;
    #pragma unroll
    for (int n = 0; n < 64; n += 8) {
        a0 = fmaf(sa[n + 0], __bfloat162float(tvp[(size_t)(n + 0) * DD]), a0);
        a1 = fmaf(sa[n + 1], __bfloat162float(tvp[(size_t)(n + 1) * DD]), a1);
        a2 = fmaf(sa[n + 2], __bfloat162float(tvp[(size_t)(n + 2) * DD]), a2);
        a3 = fmaf(sa[n + 3], __bfloat162float(tvp[(size_t)(n + 3) * DD]), a3);
        a4 = fmaf(sa[n + 4], __bfloat162float(tvp[(size_t)(n + 4) * DD]), a4);
        a5 = fmaf(sa[n + 5], __bfloat162float(tvp[(size_t)(n + 5) * DD]), a5);
        a6 = fmaf(sa[n + 6], __bfloat162float(tvp[(size_t)(n + 6) * DD]), a6);
        a7 = fmaf(sa[n + 7], __bfloat162float(tvp[(size_t)(n + 7) * DD]), a7);
    }
    atomicAdd(&g_fuse[b * DD + t], ((a0 + a1) + (a2 + a3)) + ((a4 + a5) + (a6 + a7)));
}

__global__ __launch_bounds__(256) void kLogits(
    float* __restrict__ out, const float* __restrict__ ow, const float* __restrict__ ob)
{
    const int b = blockIdx.x, t = threadIdx.x;
    __shared__ float red[8];
    float v = g_fuse[b * DD + t] * ow[t];
    #pragma unroll
    for (int o = 16; o; o >>= 1) v += __shfl_xor_sync(0xffffffffu, v, o);
    if ((t & 31) == 0) red[t >> 5] = v;
    __syncthreads();
    if (t == 0) {
        float s = 0.0f;
        #pragma unroll
        for (int w = 0; w < 8; ++w) s += red[w];
        out[b] = s + ob[0];
    }
}

extern "C" void kernel_launch(void* const* d_in, const int* in_sizes, int n_in,
                              void* d_out, int out_size)
{
    const int*   head = (const int*)d_in[0];
    const int*   tail = (const int*)d_in[1];
    const float* emb  = (const float*)d_in[2];
    const float* rela = (const float*)d_in[3];
    const float* fc_w = (const float*)d_in[4];
    const float* fc_b = (const float*)d_in[5];
    const float* aw1  = (const float*)d_in[6];
    const float* ab1  = (const float*)d_in[7];
    const float* aw2  = (const float*)d_in[8];
    const float* ab2  = (const float*)d_in[9];
    const float* ow   = (const float*)d_in[10];
    const float* ob   = (const float*)d_in[11];

    float* out        = (float*)d_out;
    float* out_logits = out;
    float* out_attn   = out + BB;
    float* out_ns     = out + BB + BB * NN;

    cudaFuncSetAttribute(kMain, cudaFuncAttributeMaxDynamicSharedMemorySize, SMEM_M_BYTES);

    kPre   <<<132,   256>>>(head, tail, emb, rela, fc_w, fc_b);
    kW1T   <<<128,   256>>>(aw1);
    kRWT   <<<32,    256>>>();
    kMain  <<<BB*WW, 256, SMEM_M_BYTES>>>(ab1, aw2, ab2, out_ns);
    kAtt   <<<BB,    256>>>(out_attn);
    kFuse  <<<BB*64, 256>>>(out_attn);
    kLogits<<<BB,    256>>>(out_logits, ow, ob);
}

// round 13
// speedup vs baseline: 1.3451x; 1.1246x over previous
#include <cuda_runtime.h>
#include <cuda_bf16.h>
#include <cstdint>
#include <cstddef>

#define BB   16
#define WW   64
#define VV   64
#define DD   256
#define RR   64
#define NN   (WW*VV)
#define PAD  68

typedef unsigned long long ull;

__device__ float g_A   [BB*WW*DD];
__device__ float g_BtT [BB*DD*VV];
__device__ float g_relaT[DD*RR];
__device__ float g_AW  [BB*WW*DD];
__device__ float g_BW  [BB*VV*DD];
__device__ float g_RW  [RR*DD];
__device__ uint32_t g_w1bT [DD*DD/2];
__device__ uint32_t g_rwbHi[DD*RR/2];
__device__ __nv_bfloat16 g_tvh[(size_t)BB*NN*DD];
__device__ float g_att [BB*NN];
__device__ float g_fuse[BB*DD];

__device__ __forceinline__ float tanh_fast(float x) {
    float y; asm("tanh.approx.f32 %0, %1;" : "=f"(y) : "f"(x)); return y;
}
__device__ __forceinline__ ull fma2(ull a, ull b, ull c) {
    ull d; asm("fma.rn.f32x2 %0, %1, %2, %3;" : "=l"(d) : "l"(a), "l"(b), "l"(c)); return d;
}
__device__ __forceinline__ ull pack2(float x) {
    ull r; asm("mov.b64 %0, {%1, %1};" : "=l"(r) : "f"(x)); return r;
}
__device__ __forceinline__ float2 unpack2(ull v) {
    float2 f; asm("mov.b64 {%0, %1}, %2;" : "=f"(f.x), "=f"(f.y) : "l"(v)); return f;
}
__device__ __forceinline__ uint32_t smem_u32(const void* p) {
    uint32_t a;
    asm("{ .reg .u64 tmp; cvta.to.shared.u64 tmp, %1; cvt.u32.u64 %0, tmp; }" : "=r"(a) : "l"(p));
    return a;
}
__device__ __forceinline__ void cp_async16(uint32_t daddr, const void* src) {
    asm volatile("cp.async.cg.shared.global [%0], [%1], 16;" :: "r"(daddr), "l"(src) : "memory");
}
#define CP_COMMIT() asm volatile("cp.async.commit_group;" ::: "memory")
#define CP_WAIT0()  asm volatile("cp.async.wait_group 0;" ::: "memory")
#define CP_WAIT1()  asm volatile("cp.async.wait_group 1;" ::: "memory")

__device__ __forceinline__ void mma_bf16(float c[4],
    uint32_t a0, uint32_t a1, uint32_t a2, uint32_t a3, uint32_t b0, uint32_t b1)
{
    asm volatile(
        "mma.sync.aligned.m16n8k16.row.col.f32.bf16.bf16.f32 "
        "{%0,%1,%2,%3}, {%4,%5,%6,%7}, {%8,%9}, {%0,%1,%2,%3};"
        : "+f"(c[0]), "+f"(c[1]), "+f"(c[2]), "+f"(c[3])
        : "r"(a0), "r"(a1), "r"(a2), "r"(a3), "r"(b0), "r"(b1));
}
__device__ __forceinline__ uint32_t pkbf2(float a, float b) {
    return (uint32_t)__bfloat16_as_ushort(__float2bfloat16_rn(a))
         | ((uint32_t)__bfloat16_as_ushort(__float2bfloat16_rn(b)) << 16);
}

__global__ __launch_bounds__(256) void kW1T(const float* __restrict__ aw1)
{
    const int p = blockIdx.x, n = threadIdx.x;
    g_w1bT[n * 128 + p] = pkbf2(aw1[(2 * p) * DD + n], aw1[(2 * p + 1) * DD + n]);
}

__global__ __launch_bounds__(256) void kRWT()
{
    const int p = blockIdx.x, n = threadIdx.x;
    g_rwbHi[n * 32 + p] = pkbf2(g_RW[(2 * p) * DD + n], g_RW[(2 * p + 1) * DD + n]);
}

__global__ __launch_bounds__(256) void kPre(
    const int* __restrict__ head, const int* __restrict__ tail,
    const float* __restrict__ emb, const float* __restrict__ rela,
    const float* __restrict__ fc_w, const float* __restrict__ fc_b)
{
    __shared__ float sX[16][257];
    const int g = blockIdx.x, t = threadIdx.x;
    const int kind = (g < 64) ? 0 : (g < 128 ? 1 : 2);
    const int row0 = ((kind == 0) ? g : (kind == 1) ? (g - 64) : (g - 128)) * 16;

    #pragma unroll 4
    for (int rr = 0; rr < 16; ++rr) {
        const int row = row0 + rr;
        float v;
        if (kind == 0)      v = emb[(size_t)head[row] * DD + t];
        else if (kind == 1) v = emb[(size_t)tail[row] * DD + t];
        else                v = rela[row * DD + t];
        sX[rr][t] = v;
        if (kind == 0) g_A[row * DD + t] = v;
    }
    __syncthreads();

    const float* Wp = fc_w + (size_t)kind * DD * DD;
    float acc[16];
    #pragma unroll
    for (int r = 0; r < 16; ++r) acc[r] = (kind == 0) ? fc_b[t] : 0.0f;
    #pragma unroll 4
    for (int k = 0; k < DD; ++k) {
        const float wv = Wp[k * DD + t];
        #pragma unroll
        for (int r = 0; r < 16; ++r) acc[r] = fmaf(sX[r][k], wv, acc[r]);
    }
    float* dst = (kind == 0) ? g_AW : (kind == 1) ? g_BW : g_RW;
    #pragma unroll
    for (int r = 0; r < 16; ++r) dst[(row0 + r) * DD + t] = acc[r];

    if (kind != 0) {
        float* dstT = (kind == 1)
            ? (g_BtT + (size_t)(row0 >> 6) * DD * VV + (row0 & 63))
            : (g_relaT + row0);
        #pragma unroll
        for (int it = 0; it < 4; ++it) {
            const int f = it * 256 + t;
            const int d = f >> 2, q = f & 3;
            float4 v;
            v.x = sX[q * 4 + 0][d]; v.y = sX[q * 4 + 1][d];
            v.z = sX[q * 4 + 2][d]; v.w = sX[q * 4 + 3][d];
            *(float4*)&dstT[d * 64 + q * 4] = v;
        }
    }
}

// ---------------------------------------------------------------------------
// kMain: 1024 blocks x 256, 2 CTAs/SM (smem 101632 B, regs <=128).
// RA (9216 floats) reused: GEMM1 4 bufs [32][68] -> RW-hi [256][36]u32 -> w1.
// ---------------------------------------------------------------------------
#define SM_RA    0
#define SM_SP    9216
#define SM_PAH   13568
#define SM_AH    15872
#define SM_SA    24320
#define SM_SAW   24576
#define SM_SB1   24832
#define SM_SW2   25088
#define SM_SRED  25344
#define SMEM_M_FLOATS 25408
#define SMEM_M_BYTES  (SMEM_M_FLOATS * 4)

__global__ __launch_bounds__(256, 2) void kMain(
    const float* __restrict__ att_b1, const float* __restrict__ att_w2,
    const float* __restrict__ att_b2, float* __restrict__ out_ns)
{
    const int t  = threadIdx.x;
    const int b  = blockIdx.x >> 6;
    const int i  = blockIdx.x & 63;
    const int lane = t & 31, wid = t >> 5;
    const int tx = t & 15, ty = t >> 4;
    const int j0g = ty * 4, r0 = tx * 4;
    const int gid = lane >> 2, tid4 = lane & 3;
    const int wm  = (wid & 3) * 16;
    const int wnl = (wid >> 2) * 32;

    extern __shared__ float sm[];
    float*    sRA  = sm + SM_RA;
    float*    sP   = sm + SM_SP;
    uint32_t* sPAH = (uint32_t*)(sm + SM_PAH);
    uint32_t* sAhi = (uint32_t*)(sm + SM_AH);    // [64][132] u32
    float*    sA   = sm + SM_SA;
    float*    sAW  = sm + SM_SAW;
    float*    sb1  = sm + SM_SB1;
    float*    sw2  = sm + SM_SW2;
    float*    sred = sm + SM_SRED;

    const int rowA = b * WW + i;
    sA [t] = g_A [rowA * DD + t];
    sAW[t] = g_AW[rowA * DD + t];
    sb1[t] = att_b1[t];
    sw2[t] = att_w2[t];
    __syncthreads();

    // ---- GEMM1: scalar fp32, 8 k-chunks of 32d, pipelined fills ----
    // buffers in RA: hb0[32][68], rb0, hb1, rb1
    const float* btT = g_BtT + (size_t)b * DD * VV;
    float* hb[2] = { sRA, sRA + 4352 };
    float* rb[2] = { sRA + 2176, sRA + 6528 };
    const int fd = t >> 4;            // fill row (per it: +16)
    const int fc = (t & 15) * 4;      // fill col

    float4 hpre[2];
    // prologue: STS h0 (scaled), prefetch h1 regs, cp.async r0, r1
    #pragma unroll
    for (int it = 0; it < 2; ++it) {
        const int d = it * 16 + fd;
        float4 v = *(const float4*)(btT + d * 64 + fc);
        const float sa = sA[d];
        v.x *= sa; v.y *= sa; v.z *= sa; v.w *= sa;
        *(float4*)&hb[0][d * PAD + fc] = v;
    }
    #pragma unroll
    for (int it = 0; it < 2; ++it)
        hpre[it] = *(const float4*)(btT + (32 + it * 16 + fd) * 64 + fc);
    #pragma unroll
    for (int s = 0; s < 2; ++s) {
        const uint32_t rB = smem_u32(rb[s]);
        #pragma unroll
        for (int it = 0; it < 2; ++it) {
            const int d = it * 16 + fd;
            cp_async16(rB + (uint32_t)(d * PAD + fc) * 4, g_relaT + (s * 32 + d) * 64 + fc);
        }
        CP_COMMIT();
    }

    ull c1[4][2];
    #pragma unroll
    for (int u = 0; u < 4; ++u) { c1[u][0] = 0ull; c1[u][1] = 0ull; }

    for (int kc = 0; kc < 8; ++kc) {
        if (kc < 7) { CP_WAIT1(); } else { CP_WAIT0(); }
        __syncthreads();
        const float* hh = hb[kc & 1];
        const float* rr = rb[kc & 1];
        #pragma unroll 4
        for (int d = 0; d < 32; ++d) {
            const float4 h4 = *(const float4*)&hh[d * PAD + j0g];
            const ulonglong2 r2 = *(const ulonglong2*)&rr[d * PAD + r0];
            const ull hp[4] = {pack2(h4.x), pack2(h4.y), pack2(h4.z), pack2(h4.w)};
            #pragma unroll
            for (int u = 0; u < 4; ++u) {
                c1[u][0] = fma2(hp[u], r2.x, c1[u][0]);
                c1[u][1] = fma2(hp[u], r2.y, c1[u][1]);
            }
        }
        __syncthreads();
        if (kc < 7) {
            // STS h(kc+1) scaled into hb[(kc+1)&1]
            float* hd = hb[(kc + 1) & 1];
            #pragma unroll
            for (int it = 0; it < 2; ++it) {
                const int d = it * 16 + fd;
                const float sa = sA[(kc + 1) * 32 + d];
                float4 v = hpre[it];
                v.x *= sa; v.y *= sa; v.z *= sa; v.w *= sa;
                *(float4*)&hd[d * PAD + fc] = v;
            }
            if (kc < 6) {
                #pragma unroll
                for (int it = 0; it < 2; ++it)
                    hpre[it] = *(const float4*)(btT + ((kc + 2) * 32 + it * 16 + fd) * 64 + fc);
                const uint32_t rB = smem_u32(rb[kc & 1]);
                #pragma unroll
                for (int it = 0; it < 2; ++it) {
                    const int d = it * 16 + fd;
                    cp_async16(rB + (uint32_t)(d * PAD + fc) * 4,
                               g_relaT + ((kc + 2) * 32 + d) * 64 + fc);
                }
                CP_COMMIT();
            }
        }
    }
    #pragma unroll
    for (int u = 0; u < 4; ++u) {
        const float2 lo = unpack2(c1[u][0]);
        const float2 hi = unpack2(c1[u][1]);
        *(float4*)&sP[(j0g + u) * PAD + r0] = make_float4(lo.x, lo.y, hi.x, hi.y);
    }
    __syncthreads();

    // RW-hi full image -> RA ([256][36] u32), overlaps softmax + ns writes
    {
        const uint32_t hB = smem_u32(sRA);
        #pragma unroll
        for (int it = 0; it < 8; ++it) {
            const int idx = it * 256 + t;   // 2048 uint4
            const int n  = idx >> 3;
            const int q4 = (idx & 7) * 4;
            cp_async16(hB + (uint32_t)(n * 144 + q4 * 4), g_rwbHi + n * 32 + q4);
        }
        CP_COMMIT();
    }

    // ---- softmax + pack P (hi only) ----
    {
        const int j = t >> 2, q = t & 3;
        const float nul = sP[j * PAD + 63];
        float v[16];
        float mx = -1e30f;
        #pragma unroll
        for (int m = 0; m < 16; ++m) {
            float s = sP[j * PAD + q * 16 + m];
            s = (s <= nul) ? -1e10f : s;
            v[m] = s;
            mx = fmaxf(mx, s);
        }
        mx = fmaxf(mx, __shfl_xor_sync(0xffffffffu, mx, 1));
        mx = fmaxf(mx, __shfl_xor_sync(0xffffffffu, mx, 2));
        float se = 0.0f;
        #pragma unroll
        for (int m = 0; m < 16; ++m) { v[m] = expf(v[m] - mx); se += v[m]; }
        se += __shfl_xor_sync(0xffffffffu, se, 1);
        se += __shfl_xor_sync(0xffffffffu, se, 2);
        const float inv = 1.0f / se;
        #pragma unroll
        for (int m = 0; m < 16; ++m) { v[m] *= inv; sP[j * PAD + q * 16 + m] = v[m]; }
        #pragma unroll
        for (int mm = 0; mm < 8; ++mm)
            sPAH[j * 36 + q * 8 + mm] = pkbf2(v[2 * mm], v[2 * mm + 1]);
    }
    __syncthreads();

    const size_t ns_base = ((size_t)(b * NN + i * VV)) * RR;
    #pragma unroll
    for (int it = 0; it < 16; ++it) {
        const int l = it * 256 + t;
        out_ns[ns_base + (size_t)(l >> 6) * RR + (l & 63)] = sP[(l >> 6) * PAD + (l & 63)];
    }
    CP_WAIT0();
    __syncthreads();

    // ---- GEMM2: PV = P @ RW, pure bf16 single pass, 4 n-chunks ----
    const uint32_t* rwH = (const uint32_t*)sRA;
    const int pr0 = (wm + gid) * 36;
    const int pr1 = (wm + gid + 8) * 36;
    const int row0 = wm + gid, row1 = wm + gid + 8;
    const size_t tvb0 = ((size_t)(b * NN + i * VV + row0)) * DD;
    const size_t tvb1 = ((size_t)(b * NN + i * VV + row1)) * DD;
    const float* bwr0 = g_BW + (size_t)(b * VV + row0) * DD;
    const float* bwr1 = g_BW + (size_t)(b * VV + row1) * DD;
    uint32_t* tvu = (uint32_t*)g_tvh;

    for (int c = 0; c < 4; ++c) {
        float a2[4][4];
        #pragma unroll
        for (int nt = 0; nt < 4; ++nt)
            #pragma unroll
            for (int e = 0; e < 4; ++e) a2[nt][e] = 0.0f;

        #pragma unroll
        for (int ks = 0; ks < 4; ++ks) {
            const int gp = ks * 8 + tid4;
            const uint32_t h0 = sPAH[pr0 + gp];
            const uint32_t h1 = sPAH[pr1 + gp];
            const uint32_t h2 = sPAH[pr0 + gp + 4];
            const uint32_t h3 = sPAH[pr1 + gp + 4];
            #pragma unroll
            for (int nt = 0; nt < 4; ++nt) {
                const int n = c * 64 + wnl + nt * 8 + gid;
                mma_bf16(a2[nt], h0, h1, h2, h3, rwH[n * 36 + gp], rwH[n * 36 + gp + 4]);
            }
        }

        // tv epilogue -> g_tvh + sAhi (bf16 hi)
        #pragma unroll
        for (int nt = 0; nt < 4; ++nt) {
            const int col = c * 64 + wnl + nt * 8 + 2 * tid4;
            const float aw0 = sAW[col], aw1v = sAW[col + 1];
            const float2 bw0 = *(const float2*)(bwr0 + col);
            const float2 bw1 = *(const float2*)(bwr1 + col);
            const uint32_t u0 = pkbf2(tanh_fast(a2[nt][0] + aw0 + bw0.x),
                                      tanh_fast(a2[nt][1] + aw1v + bw0.y));
            const uint32_t u1 = pkbf2(tanh_fast(a2[nt][2] + aw0 + bw1.x),
                                      tanh_fast(a2[nt][3] + aw1v + bw1.y));
            tvu[(tvb0 + col) >> 1] = u0;
            tvu[(tvb1 + col) >> 1] = u1;
            sAhi[row0 * 132 + (col >> 1)] = u0;
            sAhi[row1 * 132 + (col >> 1)] = u1;
        }
    }
    __syncthreads();   // sAhi complete; RA (RW) free

    // w1 chunk 0 fill ([64][132] u32 in RA)
    {
        const uint32_t wB = smem_u32(sRA);
        #pragma unroll
        for (int it = 0; it < 8; ++it) {
            const int idx = it * 256 + t;
            const int n  = idx >> 5;
            const int q4 = (idx & 31) * 4;
            cp_async16(wB + (uint32_t)(n * 528 + q4 * 4), g_w1bT + n * 128 + q4);
        }
        CP_COMMIT();
    }

    // ---- GEMM3: 4 n-chunks of 64 cols, A = bf16-hi ----
    const int ar0 = (wm + gid) * 132;
    const int ar1 = (wm + gid + 8) * 132;
    const uint32_t* wb = (const uint32_t*)sRA;
    float p0 = 0.0f, p1 = 0.0f;

    for (int c = 0; c < 4; ++c) {
        CP_WAIT0();
        __syncthreads();

        float a3[4][4];
        #pragma unroll
        for (int nt = 0; nt < 4; ++nt)
            #pragma unroll
            for (int e = 0; e < 4; ++e) a3[nt][e] = 0.0f;

        #pragma unroll 4
        for (int ks = 0; ks < 16; ++ks) {
            const int gp = ks * 8 + tid4;
            const uint32_t h0 = sAhi[ar0 + gp];
            const uint32_t h1 = sAhi[ar1 + gp];
            const uint32_t h2 = sAhi[ar0 + gp + 4];
            const uint32_t h3 = sAhi[ar1 + gp + 4];
            #pragma unroll
            for (int nt = 0; nt < 4; ++nt) {
                const int nl = wnl + nt * 8 + gid;
                mma_bf16(a3[nt], h0, h1, h2, h3, wb[nl * 132 + gp], wb[nl * 132 + gp + 4]);
            }
        }
        __syncthreads();

        if (c < 3) {
            const uint32_t wB = smem_u32(sRA);
            #pragma unroll
            for (int it = 0; it < 8; ++it) {
                const int idx = it * 256 + t;
                const int n  = idx >> 5;
                const int q4 = (idx & 31) * 4;
                cp_async16(wB + (uint32_t)(n * 528 + q4 * 4),
                           g_w1bT + (size_t)((c + 1) * 64 + n) * 128 + q4);
            }
            CP_COMMIT();
        }

        #pragma unroll
        for (int nt = 0; nt < 4; ++nt) {
            const int col = c * 64 + wnl + nt * 8 + 2 * tid4;
            p0 = fmaf(tanh_fast(a3[nt][0] + sb1[col]),     sw2[col],     p0);
            p0 = fmaf(tanh_fast(a3[nt][1] + sb1[col + 1]), sw2[col + 1], p0);
            p1 = fmaf(tanh_fast(a3[nt][2] + sb1[col]),     sw2[col],     p1);
            p1 = fmaf(tanh_fast(a3[nt][3] + sb1[col + 1]), sw2[col + 1], p1);
        }
    }

    // ---- reduce att partial sums ----
    p0 += __shfl_xor_sync(0xffffffffu, p0, 1);
    p0 += __shfl_xor_sync(0xffffffffu, p0, 2);
    p1 += __shfl_xor_sync(0xffffffffu, p1, 1);
    p1 += __shfl_xor_sync(0xffffffffu, p1, 2);

    if (wid < 4) {
        if (tid4 == 0) { sred[wm + gid] = p0; sred[wm + gid + 8] = p1; }
    }
    __syncthreads();
    if (wid >= 4) {
        if (tid4 == 0) { sred[wm + gid] += p0; sred[wm + gid + 8] += p1; }
    }
    __syncthreads();
    if (t < 64)
        g_att[b * NN + i * VV + t] = sred[t] + att_b2[0];
}

__global__ __launch_bounds__(256) void kAtt(float* __restrict__ out_attn)
{
    const int b = blockIdx.x, t = threadIdx.x;
    __shared__ float red[8];
    float vals[16];
    float mx = -1e30f;
    #pragma unroll
    for (int it = 0; it < 16; ++it) {
        vals[it] = g_att[b * NN + it * 256 + t];
        mx = fmaxf(mx, vals[it]);
    }
    #pragma unroll
    for (int o = 16; o; o >>= 1) mx = fmaxf(mx, __shfl_xor_sync(0xffffffffu, mx, o));
    if ((t & 31) == 0) red[t >> 5] = mx;
    __syncthreads();
    float bm = red[0];
    #pragma unroll
    for (int w = 1; w < 8; ++w) bm = fmaxf(bm, red[w]);
    __syncthreads();
    float s = 0.0f;
    #pragma unroll
    for (int it = 0; it < 16; ++it) { vals[it] = expf(vals[it] - bm); s += vals[it]; }
    #pragma unroll
    for (int o = 16; o; o >>= 1) s += __shfl_xor_sync(0xffffffffu, s, o);
    if ((t & 31) == 0) red[t >> 5] = s;
    __syncthreads();
    float bs = 0.0f;
    #pragma unroll
    for (int w = 0; w < 8; ++w) bs += red[w];
    const float inv = 1.0f / bs;
    #pragma unroll
    for (int it = 0; it < 16; ++it)
        out_attn[b * NN + it * 256 + t] = vals[it] * inv;
    g_fuse[b * DD + t] = 0.0f;
}

__global__ __launch_bounds__(256) void kFuse(const float* __restrict__ attn)
{
    const int b = blockIdx.x >> 6, ch = blockIdx.x & 63, t = threadIdx.x;
    __shared__ float sa[64];
    const int n0 = ch * 64;
    if (t < 64) sa[t] = attn[b * NN + n0 + t];
    __syncthreads();

    const __nv_bfloat16* tvp = g_tvh + ((size_t)(b * NN + n0)) * DD + t;
    float a0 = 0, a1 = 0, a2 = 0, a3 = 0, a4 = 0, a5 = 0, a6 = 0, a7 = 0;
    #pragma unroll
    for (int n = 0; n < 64; n += 8) {
        a0 = fmaf(sa[n + 0], __bfloat162float(tvp[(size_t)(n + 0) * DD]), a0);
        a1 = fmaf(sa[n + 1], __bfloat162float(tvp[(size_t)(n + 1) * DD]), a1);
        a2 = fmaf(sa[n + 2], __bfloat162float(tvp[(size_t)(n + 2) * DD]), a2);
        a3 = fmaf(sa[n + 3], __bfloat162float(tvp[(size_t)(n + 3) * DD]), a3);
        a4 = fmaf(sa[n + 4], __bfloat162float(tvp[(size_t)(n + 4) * DD]), a4);
        a5 = fmaf(sa[n + 5], __bfloat162float(tvp[(size_t)(n + 5) * DD]), a5);
        a6 = fmaf(sa[n + 6], __bfloat162float(tvp[(size_t)(n + 6) * DD]), a6);
        a7 = fmaf(sa[n + 7], __bfloat162float(tvp[(size_t)(n + 7) * DD]), a7);
    }
    atomicAdd(&g_fuse[b * DD + t], ((a0 + a1) + (a2 + a3)) + ((a4 + a5) + (a6 + a7)));
}

__global__ __launch_bounds__(256) void kLogits(
    float* __restrict__ out, const float* __restrict__ ow, const float* __restrict__ ob)
{
    const int b = blockIdx.x, t = threadIdx.x;
    __shared__ float red[8];
    float v = g_fuse[b * DD + t] * ow[t];
    #pragma unroll
    for (int o = 16; o; o >>= 1) v += __shfl_xor_sync(0xffffffffu, v, o);
    if ((t & 31) == 0) red[t >> 5] = v;
    __syncthreads();
    if (t == 0) {
        float s = 0.0f;
        #pragma unroll
        for (int w = 0; w < 8; ++w) s += red[w];
        out[b] = s + ob[0];
    }
}

extern "C" void kernel_launch(void* const* d_in, const int* in_sizes, int n_in,
                              void* d_out, int out_size)
{
    const int*   head = (const int*)d_in[0];
    const int*   tail = (const int*)d_in[1];
    const float* emb  = (const float*)d_in[2];
    const float* rela = (const float*)d_in[3];
    const float* fc_w = (const float*)d_in[4];
    const float* fc_b = (const float*)d_in[5];
    const float* aw1  = (const float*)d_in[6];
    const float* ab1  = (const float*)d_in[7];
    const float* aw2  = (const float*)d_in[8];
    const float* ab2  = (const float*)d_in[9];
    const float* ow   = (const float*)d_in[10];
    const float* ob   = (const float*)d_in[11];

    float* out        = (float*)d_out;
    float* out_logits = out;
    float* out_attn   = out + BB;
    float* out_ns     = out + BB + BB * NN;

    cudaFuncSetAttribute(kMain, cudaFuncAttributeMaxDynamicSharedMemorySize, SMEM_M_BYTES);

    kPre   <<<132,   256>>>(head, tail, emb, rela, fc_w, fc_b);
    kW1T   <<<128,   256>>>(aw1);
    kRWT   <<<32,    256>>>();
    kMain  <<<BB*WW, 256, SMEM_M_BYTES>>>(ab1, aw2, ab2, out_ns);
    kAtt   <<<BB,    256>>>(out_attn);
    kFuse  <<<BB*64, 256>>>(out_attn);
    kLogits<<<BB,    256>>>(out_logits, ow, ob);
}